// round 3
// baseline (speedup 1.0000x reference)
#include <cuda_runtime.h>
#include <cuda_bf16.h>
#include <cstdint>

// ---------------- problem constants ----------------
#define SEQ    512
#define BATCH  64
#define IN_W   256
#define SW     1024
#define OUT_W  256

// ---------------- kernel config --------------------
#define P_CTAS   64      // persistent CTAs; each owns JS output columns
#define NTHREADS 256     // 8 warps
#define JS       16      // output columns per CTA (64*16 = 1024)
#define KCH      128     // K-chunk for activation staging
#define NCHUNKS  (SW / KCH)   // 8
#define PADC     1032    // padded row stride (elems) -> conflict-free LDS

#define LIN_F 0.99999f
__device__ __constant__ float EPS_F = (float)(1.0 - 0.99999);

// ---------------- global scratch (static device arrays; no allocs) ------
__device__ float          d_Sf[2][BATCH * SW];   // fp32 state (ping-pong)
__device__ __nv_bfloat16  d_Sh[2][BATCH * SW];   // bf16 shadow of state
__device__ __nv_bfloat16  d_H[BATCH * SW];       // hidden activations (bf16)
__device__ int            d_inv[SW];             // inverse permutation
__device__ unsigned       d_count;               // grid barrier counter

// ---------------- helpers ----------------
static __device__ __forceinline__ unsigned smem_u32(const void* p) {
    return (unsigned)__cvta_generic_to_shared(p);
}

__device__ __forceinline__ void gbar(unsigned& barcnt) {
    __syncthreads();
    if (threadIdx.x == 0) {
        // release-arrive: no-return reduction with release semantics
        asm volatile("red.release.gpu.global.add.u32 [%0], 1;" :: "l"(&d_count) : "memory");
        unsigned target = (barcnt + 1u) * (unsigned)P_CTAS;
        unsigned v;
        while (true) {
            asm volatile("ld.acquire.gpu.u32 %0, [%1];" : "=r"(v) : "l"(&d_count) : "memory");
            if (v >= target) break;
            __nanosleep(64);
        }
    }
    barcnt++;
    __syncthreads();
}

// stage one K-chunk of the [64 x 1024] bf16 activation into padded SMEM (L2 path)
__device__ __forceinline__ void fill_chunk(__nv_bfloat16* Act,
                                           const __nv_bfloat16* __restrict__ actg,
                                           int c, int tid) {
    // chunk = 64 rows x 128 cols x 2B = 16KB = 1024 x 16B transfers
#pragma unroll
    for (int q = 0; q < 4; q++) {
        int e   = tid + q * NTHREADS;       // 0..1023
        int row = e >> 4;                   // 16 x 16B per row-chunk
        int seg = e & 15;
        unsigned dst = smem_u32(Act + row * PADC + c * KCH + seg * 8);
        const void* src = (const void*)(actg + row * SW + c * KCH + seg * 8);
        asm volatile("cp.async.cg.shared.global [%0], [%1], 16;\n" :: "r"(dst), "l"(src));
    }
}

// one K-chunk of mma.sync m16n8k16 bf16 (8 k-steps)
__device__ __forceinline__ void mma_chunk(const __nv_bfloat16* __restrict__ Act,
                                          const __nv_bfloat16* __restrict__ Ws,
                                          int kbase, int r0, int r1, int brow, int tc,
                                          float& c0, float& c1, float& c2, float& c3) {
    const uint32_t* A0 = reinterpret_cast<const uint32_t*>(Act + r0 * PADC + kbase + tc);
    const uint32_t* A1 = reinterpret_cast<const uint32_t*>(Act + r1 * PADC + kbase + tc);
    const uint32_t* Bp = reinterpret_cast<const uint32_t*>(Ws + brow * PADC + kbase + tc);
#pragma unroll
    for (int i = 0; i < KCH / 16; i++) {
        uint32_t a0 = A0[i * 8], a2 = A0[i * 8 + 4];
        uint32_t a1 = A1[i * 8], a3 = A1[i * 8 + 4];
        uint32_t b0 = Bp[i * 8], b1 = Bp[i * 8 + 4];
        asm("mma.sync.aligned.m16n8k16.row.col.f32.bf16.bf16.f32 "
            "{%0,%1,%2,%3}, {%4,%5,%6,%7}, {%8,%9}, {%0,%1,%2,%3};\n"
            : "+f"(c0), "+f"(c1), "+f"(c2), "+f"(c3)
            : "r"(a0), "r"(a1), "r"(a2), "r"(a3), "r"(b0), "r"(b1));
    }
}

// full GEMM for one phase: acc = act[64x1024] @ Wslice^T  (pipelined staging)
__device__ __forceinline__ void gemm_full(const __nv_bfloat16* __restrict__ actg,
                                          __nv_bfloat16* Act,
                                          const __nv_bfloat16* __restrict__ Ws,
                                          int tid, int r0, int r1, int brow, int tc,
                                          float& c0, float& c1, float& c2, float& c3) {
    c0 = c1 = c2 = c3 = 0.f;
    fill_chunk(Act, actg, 0, tid);
    asm volatile("cp.async.commit_group;\n" ::: "memory");
#pragma unroll 1
    for (int c = 0; c < NCHUNKS; c++) {
        if (c + 1 < NCHUNKS) {
            fill_chunk(Act, actg, c + 1, tid);
            asm volatile("cp.async.commit_group;\n" ::: "memory");
            asm volatile("cp.async.wait_group 1;\n" ::: "memory");
        } else {
            asm volatile("cp.async.wait_group 0;\n" ::: "memory");
        }
        __syncthreads();
        mma_chunk(Act, Ws, c * KCH, r0, r1, brow, tc, c0, c1, c2, c3);
        __syncthreads();
    }
}

// ---------------- setup: inverse perm, S0, barrier reset ----------------
__global__ void setup_kernel(const float* __restrict__ x,
                             const float* __restrict__ init,
                             const int* __restrict__ rp) {
    int tid = blockIdx.x * blockDim.x + threadIdx.x;
    if (tid == 0) d_count = 0u;
    if (tid < SW) d_inv[rp[tid]] = tid;
    const float eps = EPS_F;
    for (int e = tid; e < BATCH * SW; e += gridDim.x * blockDim.x) {
        int b = e >> 10, p = e & (SW - 1);
        int q = rp[p];
        float v = eps * init[q];
        if (q < IN_W) v += x[b * IN_W + q];   // x[t=0]
        d_Sf[0][b * SW + p] = v;
        d_Sh[0][b * SW + p] = __float2bfloat16(v);
    }
}

// ---------------- persistent RNN kernel ----------------
__global__ void __launch_bounds__(NTHREADS, 1)
resrnn_kernel(const float* __restrict__ x,
              const float* __restrict__ W1, const float* __restrict__ b1,
              const float* __restrict__ W2, const float* __restrict__ b2,
              float* __restrict__ out, int out_size) {
    extern __shared__ __nv_bfloat16 smem[];
    __nv_bfloat16* W1s = smem;                      // [JS][PADC]
    __nv_bfloat16* W2s = smem + JS * PADC;          // [JS][PADC]
    __nv_bfloat16* Act = smem + 2 * JS * PADC;      // [BATCH][PADC]

    const int tid   = threadIdx.x;
    const int cta   = blockIdx.x;
    const int jbase = cta * JS;

    // ---- load weight slices once (fp32 -> bf16), resident for all 512 steps ----
    for (int e = tid; e < JS * (SW / 4); e += NTHREADS) {
        int n  = e / (SW / 4);
        int k4 = e % (SW / 4);
        float4 v = reinterpret_cast<const float4*>(W1 + (size_t)(jbase + n) * SW)[k4];
        __nv_bfloat16* d1 = W1s + n * PADC + k4 * 4;
        d1[0] = __float2bfloat16(v.x); d1[1] = __float2bfloat16(v.y);
        d1[2] = __float2bfloat16(v.z); d1[3] = __float2bfloat16(v.w);
        float4 w = reinterpret_cast<const float4*>(W2 + (size_t)(jbase + n) * SW)[k4];
        __nv_bfloat16* d2 = W2s + n * PADC + k4 * 4;
        d2[0] = __float2bfloat16(w.x); d2[1] = __float2bfloat16(w.y);
        d2[2] = __float2bfloat16(w.z); d2[3] = __float2bfloat16(w.w);
    }
    __syncthreads();

    // ---- per-thread static coordinates (mma.sync m16n8k16 fragment mapping) ----
    const int warp = tid >> 5, lane = tid & 31;
    const int mt = warp & 3, nt = warp >> 2;        // 4 m-tiles x 2 n-tiles
    const int g  = lane >> 2, tc = (lane & 3) * 2;
    const int r0 = mt * 16 + g, r1 = r0 + 8;        // batch rows
    const int brow = nt * 8 + g;                    // local B row (n index)
    const int jl0 = nt * 8 + tc;
    const int j0 = jbase + jl0, j1 = j0 + 1;        // global output columns
    const float bb1_0 = b1[j0], bb1_1 = b1[j1];
    const float bb2_0 = b2[j0], bb2_1 = b2[j1];
    const int ip0 = d_inv[j0], ip1 = d_inv[j1];     // scatter targets
    const float eps = EPS_F;
    unsigned barcnt = 0;

    for (int t = 0; t < SEQ; t++) {
        const int cur = t & 1, nxt = cur ^ 1;
        float c0, c1, c2, c3;

        // ================= phase 1: h = relu(S @ W1^T + b1) =================
        gemm_full(d_Sh[cur], Act, W1s, tid, r0, r1, brow, tc, c0, c1, c2, c3);
        {
            float h00 = fmaxf(c0 + bb1_0, 0.f);
            float h01 = fmaxf(c1 + bb1_1, 0.f);
            float h10 = fmaxf(c2 + bb1_0, 0.f);
            float h11 = fmaxf(c3 + bb1_1, 0.f);
            __nv_bfloat162* Hp = reinterpret_cast<__nv_bfloat162*>(d_H);
            Hp[(r0 * SW + j0) >> 1] = __floats2bfloat162_rn(h00, h01);
            Hp[(r1 * SW + j0) >> 1] = __floats2bfloat162_rn(h10, h11);
        }
        gbar(barcnt);

        // ================= phase 2: y = h @ W2^T + b2 ; fused update ========
        gemm_full(d_H, Act, W2s, tid, r0, r1, brow, tc, c0, c1, c2, c3);
        {
            float y00 = c0 + bb2_0, y01 = c1 + bb2_1;
            float y10 = c2 + bb2_0, y11 = c3 + bb2_1;
            const float* Sc = d_Sf[cur];
            float s00 = __ldcg(Sc + r0 * SW + j0);
            float s01 = __ldcg(Sc + r0 * SW + j1);
            float s10 = __ldcg(Sc + r1 * SW + j0);
            float s11 = __ldcg(Sc + r1 * SW + j1);
            float n00 = LIN_F * s00 + eps * y00;
            float n01 = LIN_F * s01 + eps * y01;
            float n10 = LIN_F * s10 + eps * y10;
            float n11 = LIN_F * s11 + eps * y11;
            if (t < SEQ - 1) {
                if (j0 < IN_W) {  // this CTA's columns receive input (jbase multiple of 16)
                    const float* xp = x + (size_t)(t + 1) * BATCH * IN_W;
                    n00 += xp[r0 * IN_W + j0]; n01 += xp[r0 * IN_W + j1];
                    n10 += xp[r1 * IN_W + j0]; n11 += xp[r1 * IN_W + j1];
                }
                float* Sn = d_Sf[nxt];
                __nv_bfloat16* Shn = d_Sh[nxt];
                Sn[r0 * SW + ip0] = n00; Shn[r0 * SW + ip0] = __float2bfloat16(n00);
                Sn[r0 * SW + ip1] = n01; Shn[r0 * SW + ip1] = __float2bfloat16(n01);
                Sn[r1 * SW + ip0] = n10; Shn[r1 * SW + ip0] = __float2bfloat16(n10);
                Sn[r1 * SW + ip1] = n11; Shn[r1 * SW + ip1] = __float2bfloat16(n11);
            } else {
                // final step: emit (outputs, last)
                float vv[4] = {n00, n01, n10, n11};
                int   bb[4] = {r0, r0, r1, r1};
                int   ii[4] = {j0, j1, j0, j1};
#pragma unroll
                for (int u = 0; u < 4; u++) {
                    int b = bb[u], i = ii[u];
                    float v = vv[u];
                    if (out_size == BATCH * (OUT_W + SW)) {           // (outputs, last)
                        out[BATCH * OUT_W + b * SW + i] = v;
                        if (i >= SW - OUT_W) out[b * OUT_W + (i - (SW - OUT_W))] = v;
                    } else if (out_size == BATCH * SW) {              // last only
                        out[b * SW + i] = v;
                    } else {                                          // outputs only
                        if (i >= SW - OUT_W) out[b * OUT_W + (i - (SW - OUT_W))] = v;
                    }
                }
            }
        }
        gbar(barcnt);
    }
}

// ---------------- launch ----------------
extern "C" void kernel_launch(void* const* d_in, const int* in_sizes, int n_in,
                              void* d_out, int out_size) {
    const float* x    = (const float*)d_in[0];
    const float* init = (const float*)d_in[1];
    const int*   rp   = (const int*)  d_in[2];
    const float* W1   = (const float*)d_in[3];
    const float* b1   = (const float*)d_in[4];
    const float* W2   = (const float*)d_in[5];
    const float* b2   = (const float*)d_in[6];

    setup_kernel<<<64, 256>>>(x, init, rp);

    const int smem_bytes = (2 * JS * PADC + BATCH * PADC) * (int)sizeof(__nv_bfloat16);
    cudaFuncSetAttribute(resrnn_kernel, cudaFuncAttributeMaxDynamicSharedMemorySize, smem_bytes);
    resrnn_kernel<<<P_CTAS, NTHREADS, smem_bytes>>>(x, W1, b1, W2, b2,
                                                    (float*)d_out, out_size);
}